// round 15
// baseline (speedup 1.0000x reference)
#include <cuda_runtime.h>
#include <math.h>

#define BS 8
#define QN 1000
#define NC 92
#define TN 300
#define QP1 1001
#define TP1 301
#define SCSZ (BS*QP1*TP1)          // 2,410,408
#define MTROW (QN+TN)              // 1300
#define CPL 10
#define CHUNK 250
#define NSTEP 1032                 // >= QN+30 drain, multiple of 8
#define SKROW 1048                 // >= NSTEP + 8 prefetch
#define FULLM 0xffffffffu
#define NEGINF (-INFINITY)
#define SLOT(k,l) (((k) >> 1) * 64 + (l) * 2 + ((k) & 1))

#define WMAIN (BS*1029)            // post: warps over (b, step 1..1029)
#define NCOL0 (BS*QP1)
#define NROW0 (BS*TN)

__device__ float2 g_sm[BS*QN];               // per-(b,q) softmax (max, sum)
__device__ float g_rwsk[BS*SKROW*320];       // rewards, skewed+paired
__device__ float g_scr[BS*SKROW*320];        // scores scratch, skewed+paired
__device__ unsigned g_pk2[BS*SKROW*32];      // 2-bit ptr codes (from dp)
__device__ int g_lbl64;

// ---------------- softmax stats + label dtype detection ----------------
__global__ void stat_kernel(const float* __restrict__ logits,
                            const unsigned* __restrict__ lbl_raw) {
    if (blockIdx.x == 0 && threadIdx.x == 0) {
        int allzero = 1;
        #pragma unroll
        for (int k = 1; k < 16; k += 2) allzero &= (lbl_raw[k] == 0u);
        g_lbl64 = allzero;
    }
    int warpId = (blockIdx.x * blockDim.x + threadIdx.x) >> 5;
    int lane = threadIdx.x & 31;
    if (warpId >= BS * QN) return;
    const float* row = logits + warpId * NC;
    float v0 = (lane < NC)      ? row[lane]      : NEGINF;
    float v1 = (lane + 32 < NC) ? row[lane + 32] : NEGINF;
    float v2 = (lane + 64 < NC) ? row[lane + 64] : NEGINF;
    float m = fmaxf(v0, fmaxf(v1, v2));
    #pragma unroll
    for (int o = 16; o; o >>= 1) m = fmaxf(m, __shfl_xor_sync(FULLM, m, o));
    float e0 = (lane < NC)      ? expf(v0 - m) : 0.f;
    float e1 = (lane + 32 < NC) ? expf(v1 - m) : 0.f;
    float e2 = (lane + 64 < NC) ? expf(v2 - m) : 0.f;
    float s = e0 + e1 + e2;
    #pragma unroll
    for (int o = 16; o; o >>= 1) s += __shfl_xor_sync(FULLM, s, o);
    if (lane == 0) g_sm[warpId] = make_float2(m, s);
}

// ---------------- cost -> skewed paired rewards ----------------
__global__ void cost_kernel(const float* __restrict__ logits,
                            const float* __restrict__ pred_boxes,
                            const int* __restrict__ tgt_labels,
                            const float* __restrict__ tgt_boxes) {
    int idx = blockIdx.x * blockDim.x + threadIdx.x;
    if (idx >= BS * QN * TN) return;
    int t = idx % TN;
    int bq = idx / TN;
    int b = bq / QN;
    int r = (bq % QN) + 1;

    float4 pb = ((const float4*)pred_boxes)[bq];
    float4 tb = ((const float4*)tgt_boxes)[b * TN + t];
    int li = b * TN + t;
    int lbl = g_lbl64 ? tgt_labels[li * 2] : tgt_labels[li];
    lbl = max(0, min(NC - 1, lbl));
    float2 ms = g_sm[bq];
    float p = expf(logits[bq * NC + lbl] - ms.x) / ms.y;

    float l1 = fabsf(pb.x - tb.x) + fabsf(pb.y - tb.y) +
               fabsf(pb.z - tb.z) + fabsf(pb.w - tb.w);

    float px1 = pb.x - 0.5f * pb.z, py1 = pb.y - 0.5f * pb.w;
    float px2 = pb.x + 0.5f * pb.z, py2 = pb.y + 0.5f * pb.w;
    float tx1 = tb.x - 0.5f * tb.z, ty1 = tb.y - 0.5f * tb.w;
    float tx2 = tb.x + 0.5f * tb.z, ty2 = tb.y + 0.5f * tb.w;

    float a1 = (px2 - px1) * (py2 - py1);
    float a2 = (tx2 - tx1) * (ty2 - ty1);
    float ltx = fmaxf(px1, tx1), lty = fmaxf(py1, ty1);
    float rbx = fminf(px2, tx2), rby = fminf(py2, ty2);
    float iw = fmaxf(rbx - ltx, 0.f), ih = fmaxf(rby - lty, 0.f);
    float inter = iw * ih;
    float uni = a1 + a2 - inter;
    float iou = inter / uni;
    float cx1 = fminf(px1, tx1), cy1 = fminf(py1, ty1);
    float cx2 = fmaxf(px2, tx2), cy2 = fmaxf(py2, ty2);
    float cw = fmaxf(cx2 - cx1, 0.f), ch = fmaxf(cy2 - cy1, 0.f);
    float ac = cw * ch;
    float giou = iou - (ac - uni) / ac;

    float cost = 5.0f * l1 - p - 2.0f * giou;
    int l = t / CPL, k = t % CPL;
    g_rwsk[(size_t)b * SKROW * 320 + (size_t)(r + l) * 320 + SLOT(k, l)] = 10000.0f - cost;
}

// ---------------- DP: one WARP per batch, wavefront; fast h1 path ----------
__global__ void __launch_bounds__(32, 1) dp_kernel() {
    int b = blockIdx.x;
    int lane = threadIdx.x;

    const float2* rwsk = (const float2*)(g_rwsk + (size_t)b * SKROW * 320);
    float2* scr = (float2*)(g_scr + (size_t)b * SKROW * 320);
    unsigned* pk2 = g_pk2 + (size_t)b * SKROW * 32;

    float prev[CPL];
    #pragma unroll
    for (int k = 0; k < CPL; k++) prev[k] = 0.f;
    float h1 = 0.f, h2 = 0.f;

    float2 B0[5], B1[5], B2[5], B3[5], B4[5], B5[5], B6[5], B7[5];

    #define LOADBUF(BUF, S)                                                     \
    {                                                                           \
        const float2* pp = rwsk + (size_t)(S) * 160 + lane;                     \
        _Pragma("unroll")                                                       \
        for (int q = 0; q < 5; q++) BUF[q] = pp[q * 32];                        \
    }

    LOADBUF(B0, 1) LOADBUF(B1, 2) LOADBUF(B2, 3) LOADBUF(B3, 4)
    LOADBUF(B4, 5) LOADBUF(B5, 6) LOADBUF(B6, 7) LOADBUF(B7, 8)

    #define STEP(S, BUF)                                                        \
    {                                                                           \
        int r = (S) - lane;                                                     \
        bool act = (lane < 30) && (r >= 1) && (r <= QN);                        \
        float X1 = __shfl_up_sync(FULLM, h1, 1);                                \
        float X2 = __shfl_up_sync(FULLM, h2, 1);                                \
        if (lane == 0) { X1 = NEGINF; X2 = 0.f; }                               \
        float rk[CPL];                                                          \
        _Pragma("unroll")                                                       \
        for (int q = 0; q < 5; q++) { rk[2*q] = BUF[q].x; rk[2*q+1] = BUF[q].y; } \
        LOADBUF(BUF, (S) + 8)                                                   \
        float dg[CPL], m[CPL];                                                  \
        dg[0] = X2 + rk[0];                                                     \
        _Pragma("unroll")                                                       \
        for (int k = 1; k < CPL; k++) dg[k] = prev[k-1] + rk[k];                \
        _Pragma("unroll")                                                       \
        for (int k = 0; k < CPL; k++) m[k] = fmaxf(dg[k], prev[k]);             \
        /* tree prefix over m only — independent of X1 (shfl shadow) */         \
        float p1_[CPL], p2_[CPL], p4_[CPL], lpf[CPL];                           \
        p1_[0] = m[0];                                                          \
        _Pragma("unroll")                                                       \
        for (int k = 1; k < CPL; k++) p1_[k] = fmaxf(m[k], m[k-1]);             \
        p2_[0] = p1_[0]; p2_[1] = p1_[1];                                       \
        _Pragma("unroll")                                                       \
        for (int k = 2; k < CPL; k++) p2_[k] = fmaxf(p1_[k], p1_[k-2]);         \
        _Pragma("unroll")                                                       \
        for (int k = 0; k < 4; k++) p4_[k] = p2_[k];                            \
        _Pragma("unroll")                                                       \
        for (int k = 4; k < CPL; k++) p4_[k] = fmaxf(p2_[k], p2_[k-4]);         \
        _Pragma("unroll")                                                       \
        for (int k = 0; k < 8; k++) lpf[k] = p4_[k];                            \
        _Pragma("unroll")                                                       \
        for (int k = 8; k < CPL; k++) lpf[k] = fmaxf(p4_[k], p4_[k-8]);         \
        h2 = h1;                                                                \
        float hn = fmaxf(lpf[CPL-1], X1);   /* critical: ready X1+4 */          \
        h1 = act ? hn : 0.f;                                                    \
        float pf[CPL];                                                          \
        _Pragma("unroll")                                                       \
        for (int k = 0; k < CPL; k++) pf[k] = fmaxf(lpf[k], X1);                \
        float2* dsc = scr + (size_t)(S) * 160 + lane;                           \
        _Pragma("unroll")                                                       \
        for (int q = 0; q < 5; q++) dsc[q * 32] = make_float2(pf[2*q], pf[2*q+1]); \
        unsigned word = 0;                                                      \
        _Pragma("unroll")                                                       \
        for (int k = 0; k < CPL; k++) {                                         \
            unsigned e = (dg[k] == pf[k]) ? 0u : ((prev[k] == pf[k]) ? 1u : 2u);\
            word |= e << (2 * k);                                               \
        }                                                                       \
        pk2[(size_t)(S) * 32 + lane] = word;                                    \
        if (act) {                                                              \
            _Pragma("unroll")                                                   \
            for (int k = 0; k < CPL; k++) prev[k] = pf[k];                      \
        }                                                                       \
    }

    #pragma unroll 1
    for (int s = 1; s <= NSTEP; s += 8) {
        STEP(s,     B0) STEP(s + 1, B1) STEP(s + 2, B2) STEP(s + 3, B3)
        STEP(s + 4, B4) STEP(s + 5, B5) STEP(s + 6, B6) STEP(s + 7, B7)
    }
    #undef STEP
    #undef LOADBUF
}

// ---------------- post v2: warp per (b, step), coalesced reads -------------
__global__ void post_kernel(float* __restrict__ out) {
    int gtid = blockIdx.x * blockDim.x + threadIdx.x;
    int gw = gtid >> 5;
    int lane = gtid & 31;

    if (gw < WMAIN) {
        int b = gw / 1029;
        int s = gw % 1029 + 1;           // step 1..1029 covers r in [1,QN], l in [0,30)
        int l = lane;
        int r = s - l;
        // coalesced loads of the whole step-row
        const float2* sp2 = (const float2*)(g_scr + (size_t)b * SKROW * 320) + (size_t)s * 160 + lane;
        float pf[CPL];
        #pragma unroll
        for (int q = 0; q < 5; q++) {
            float2 v = sp2[q * 32];
            pf[2*q] = v.x; pf[2*q+1] = v.y;
        }
        unsigned word = g_pk2[(size_t)b * SKROW * 32 + (size_t)s * 32 + lane];
        if (l < 30 && r >= 1 && r <= QN) {
            size_t rowoff = ((size_t)b * QP1 + r) * TP1 + 1 + l * CPL;
            float* dsts = out + rowoff;
            float* dstp = out + SCSZ + rowoff;
            #pragma unroll
            for (int k = 0; k < CPL; k++) {
                unsigned e = (word >> (2 * k)) & 3u;
                dsts[k] = pf[k];
                dstp[k] = (e == 0u) ? 0.f : ((e == 1u) ? -1.f : 1.f);
            }
        }
    } else {
        int x = gtid - WMAIN * 32;
        if (x < NCOL0) {
            int i = x % QP1;
            int b = x / QP1;
            size_t o = ((size_t)b * QP1 + i) * TP1;
            out[o] = 0.f;
            out[SCSZ + o] = (i == 0) ? 0.f : -1.f;
        } else if (x < NCOL0 + NROW0) {
            int y = x - NCOL0;
            int j = (y % TN) + 1;
            int b = y / TN;
            size_t o = (size_t)b * QP1 * TP1 + j;
            out[o] = 0.f;
            out[SCSZ + o] = 1.f;
        }
    }
}

// ---------------- traceback: one warp per batch, chunked smem ----------
__global__ void __launch_bounds__(32, 1) tb_kernel(float* __restrict__ out) {
    __shared__ unsigned chunkBuf[(CHUNK + 30) * 32];   // 35.8 KB

    int b = blockIdx.x;
    int lane = threadIdx.x;
    const unsigned* pk2 = g_pk2 + (size_t)b * SKROW * 32;
    float* mt = out + 2 * (size_t)SCSZ + (size_t)b * MTROW * 2;
    int r = QN, c = TN, st = 0;

    #pragma unroll 1
    for (int kk = 0; kk < QN / CHUNK; kk++) {
        int hi = QN - kk * CHUNK;
        int lo = hi - (CHUNK - 1);
        const unsigned* src = pk2 + (size_t)lo * 32;
        #pragma unroll 4
        for (int x = lane; x < (CHUNK + 30) * 32; x += 32) chunkBuf[x] = src[x];
        __syncwarp();
        if (lane == 0) {
            while (st < MTROW && r >= lo) {
                int p;
                if (c == 0) {
                    p = -1;
                } else {
                    int ci = c - 1;
                    int l = ci / CPL;
                    unsigned wd = chunkBuf[(r + l - lo) * 32 + l];
                    int e = (wd >> (2 * (ci % CPL))) & 3;
                    p = (e == 0) ? 0 : ((e == 1) ? -1 : 1);
                }
                int nr = (p == 1) ? r : r - 1;
                int nc = (p == -1) ? c : c - 1;
                bool ismatch = (p == 0);
                int oidx = (MTROW - 1 - st) * 2;
                mt[oidx]     = ismatch ? (float)nr : -1.f;
                mt[oidx + 1] = ismatch ? (float)nc : -1.f;
                r = nr; c = nc; st++;
            }
        }
        __syncwarp();
    }
    if (lane == 0) {
        while (st < MTROW) {
            int oidx = (MTROW - 1 - st) * 2;
            mt[oidx] = -1.f;
            mt[oidx + 1] = -1.f;
            st++;
        }
    }
}

extern "C" void kernel_launch(void* const* d_in, const int* in_sizes, int n_in,
                              void* d_out, int out_size) {
    const float* pred_logits = (const float*)d_in[0];
    const float* pred_boxes  = (const float*)d_in[1];
    const int*   tgt_labels  = (const int*)d_in[2];
    const float* tgt_boxes   = (const float*)d_in[3];
    float* out = (float*)d_out;

    stat_kernel<<<(BS * QN + 7) / 8, 256>>>(pred_logits, (const unsigned*)d_in[2]);
    cost_kernel<<<(BS * QN * TN + 255) / 256, 256>>>(pred_logits, pred_boxes,
                                                     tgt_labels, tgt_boxes);
    dp_kernel<<<BS, 32>>>();
    post_kernel<<<(WMAIN * 32 + NCOL0 + NROW0 + 127) / 128, 128>>>(out);
    tb_kernel<<<BS, 32>>>(out);
}

// round 16
// speedup vs baseline: 1.1807x; 1.1807x over previous
#include <cuda_runtime.h>
#include <math.h>

#define BS 8
#define QN 1000
#define NC 92
#define TN 300
#define QP1 1001
#define TP1 301
#define SCSZ (BS*QP1*TP1)          // 2,410,408
#define MTROW (QN+TN)              // 1300
#define CPL 10
#define CHUNK 125
#define NSTEP 1032                 // >= QN+30 drain, multiple of 8
#define SKROW 1048                 // >= NSTEP + 8 prefetch
#define NSACT 1029                 // active steps (r in [1,QN], l in [0,30))
#define FULLM 0xffffffffu
#define NEGINF (-INFINITY)

#define WMAIN (BS*NSACT)           // post: warps over (b, step 1..1029)
#define NCOL0 (BS*QP1)
#define NROW0 (BS*TN)
#define PBLK ((WMAIN*32 + NCOL0 + NROW0 + 127)/128)   // post blocks

__device__ float2 g_sm[BS*QN];               // per-(b,q) softmax (max, sum)
__device__ float g_rwsk[BS*SKROW*320];       // rewards, skewed+paired
__device__ float g_scr[BS*SKROW*320];        // scores scratch, skewed+paired
__device__ unsigned g_pk2[BS*SKROW*32];      // 2-bit ptr codes (from dp)
__device__ int g_lbl64;

// ---------------- softmax stats + label dtype detection ----------------
__global__ void stat_kernel(const float* __restrict__ logits,
                            const unsigned* __restrict__ lbl_raw) {
    if (blockIdx.x == 0 && threadIdx.x == 0) {
        int allzero = 1;
        #pragma unroll
        for (int k = 1; k < 16; k += 2) allzero &= (lbl_raw[k] == 0u);
        g_lbl64 = allzero;
    }
    int warpId = (blockIdx.x * blockDim.x + threadIdx.x) >> 5;
    int lane = threadIdx.x & 31;
    if (warpId >= BS * QN) return;
    const float* row = logits + warpId * NC;
    float v0 = (lane < NC)      ? row[lane]      : NEGINF;
    float v1 = (lane + 32 < NC) ? row[lane + 32] : NEGINF;
    float v2 = (lane + 64 < NC) ? row[lane + 64] : NEGINF;
    float m = fmaxf(v0, fmaxf(v1, v2));
    #pragma unroll
    for (int o = 16; o; o >>= 1) m = fmaxf(m, __shfl_xor_sync(FULLM, m, o));
    float e0 = (lane < NC)      ? expf(v0 - m) : 0.f;
    float e1 = (lane + 32 < NC) ? expf(v1 - m) : 0.f;
    float e2 = (lane + 64 < NC) ? expf(v2 - m) : 0.f;
    float s = e0 + e1 + e2;
    #pragma unroll
    for (int o = 16; o; o >>= 1) s += __shfl_xor_sync(FULLM, s, o);
    if (lane == 0) g_sm[warpId] = make_float2(m, s);
}

// ---------------- cost v2: thread-per-slot, coalesced reward stores --------
__global__ void cost_kernel(const float* __restrict__ logits,
                            const float* __restrict__ pred_boxes,
                            const int* __restrict__ tgt_labels,
                            const float* __restrict__ tgt_boxes) {
    int idx = blockIdx.x * blockDim.x + threadIdx.x;
    if (idx >= BS * NSACT * 320) return;
    int slot = idx % 320;
    int bs_ = idx / 320;
    int s = bs_ % NSACT + 1;
    int b = bs_ / NSACT;
    int l = (slot & 63) >> 1;                 // lane
    int k = ((slot >> 6) << 1) + (slot & 1);  // strip col
    int r = s - l;
    if (l >= 30 || r < 1 || r > QN) return;
    int t = l * CPL + k;
    int bq = b * QN + (r - 1);

    float4 pb = ((const float4*)pred_boxes)[bq];
    float4 tb = ((const float4*)tgt_boxes)[b * TN + t];
    int li = b * TN + t;
    int lbl = g_lbl64 ? tgt_labels[li * 2] : tgt_labels[li];
    lbl = max(0, min(NC - 1, lbl));
    float2 ms = g_sm[bq];
    float p = expf(logits[bq * NC + lbl] - ms.x) / ms.y;

    float l1 = fabsf(pb.x - tb.x) + fabsf(pb.y - tb.y) +
               fabsf(pb.z - tb.z) + fabsf(pb.w - tb.w);

    float px1 = pb.x - 0.5f * pb.z, py1 = pb.y - 0.5f * pb.w;
    float px2 = pb.x + 0.5f * pb.z, py2 = pb.y + 0.5f * pb.w;
    float tx1 = tb.x - 0.5f * tb.z, ty1 = tb.y - 0.5f * tb.w;
    float tx2 = tb.x + 0.5f * tb.z, ty2 = tb.y + 0.5f * tb.w;

    float a1 = (px2 - px1) * (py2 - py1);
    float a2 = (tx2 - tx1) * (ty2 - ty1);
    float ltx = fmaxf(px1, tx1), lty = fmaxf(py1, ty1);
    float rbx = fminf(px2, tx2), rby = fminf(py2, ty2);
    float iw = fmaxf(rbx - ltx, 0.f), ih = fmaxf(rby - lty, 0.f);
    float inter = iw * ih;
    float uni = a1 + a2 - inter;
    float iou = inter / uni;
    float cx1 = fminf(px1, tx1), cy1 = fminf(py1, ty1);
    float cx2 = fmaxf(px2, tx2), cy2 = fmaxf(py2, ty2);
    float cw = fmaxf(cx2 - cx1, 0.f), ch = fmaxf(cy2 - cy1, 0.f);
    float ac = cw * ch;
    float giou = iou - (ac - uni) / ac;

    float cost = 5.0f * l1 - p - 2.0f * giou;
    g_rwsk[(size_t)b * SKROW * 320 + (size_t)s * 320 + slot] = 10000.0f - cost;
}

// ---------------- DP: one WARP per batch, wavefront, fused chain + codes ---
__global__ void __launch_bounds__(32, 1) dp_kernel() {
    int b = blockIdx.x;
    int lane = threadIdx.x;

    const float2* rwsk = (const float2*)(g_rwsk + (size_t)b * SKROW * 320);
    float2* scr = (float2*)(g_scr + (size_t)b * SKROW * 320);
    unsigned* pk2 = g_pk2 + (size_t)b * SKROW * 32;

    float prev[CPL];
    #pragma unroll
    for (int k = 0; k < CPL; k++) prev[k] = 0.f;
    float h1 = 0.f, h2 = 0.f;

    float2 B0[5], B1[5], B2[5], B3[5], B4[5], B5[5], B6[5], B7[5];

    #define LOADBUF(BUF, S)                                                     \
    {                                                                           \
        const float2* pp = rwsk + (size_t)(S) * 160 + lane;                     \
        _Pragma("unroll")                                                       \
        for (int q = 0; q < 5; q++) BUF[q] = pp[q * 32];                        \
    }

    LOADBUF(B0, 1) LOADBUF(B1, 2) LOADBUF(B2, 3) LOADBUF(B3, 4)
    LOADBUF(B4, 5) LOADBUF(B5, 6) LOADBUF(B6, 7) LOADBUF(B7, 8)

    #define STEP(S, BUF)                                                        \
    {                                                                           \
        int r = (S) - lane;                                                     \
        bool act = (lane < 30) && (r >= 1) && (r <= QN);                        \
        float X1 = __shfl_up_sync(FULLM, h1, 1);                                \
        float X2 = __shfl_up_sync(FULLM, h2, 1);                                \
        if (lane == 0) { X1 = NEGINF; X2 = 0.f; }                               \
        float rk[CPL];                                                          \
        _Pragma("unroll")                                                       \
        for (int q = 0; q < 5; q++) { rk[2*q] = BUF[q].x; rk[2*q+1] = BUF[q].y; } \
        LOADBUF(BUF, (S) + 8)                                                   \
        /* fused sequential prefix: 30 fma-pipe ops (issue-minimal) */          \
        float dg[CPL], pf[CPL];                                                 \
        dg[0] = X2 + rk[0];                                                     \
        _Pragma("unroll")                                                       \
        for (int k = 1; k < CPL; k++) dg[k] = prev[k-1] + rk[k];                \
        pf[0] = fmaxf(fmaxf(dg[0], prev[0]), X1);                               \
        _Pragma("unroll")                                                       \
        for (int k = 1; k < CPL; k++)                                           \
            pf[k] = fmaxf(fmaxf(dg[k], prev[k]), pf[k-1]);                      \
        h2 = h1;                                                                \
        h1 = act ? pf[CPL-1] : 0.f;                                             \
        float2* dsc = scr + (size_t)(S) * 160 + lane;                           \
        _Pragma("unroll")                                                       \
        for (int q = 0; q < 5; q++) dsc[q * 32] = make_float2(pf[2*q], pf[2*q+1]); \
        unsigned word = 0;                                                      \
        _Pragma("unroll")                                                       \
        for (int k = 0; k < CPL; k++) {                                         \
            unsigned e = (dg[k] == pf[k]) ? 0u : ((prev[k] == pf[k]) ? 1u : 2u);\
            word |= e << (2 * k);                                               \
        }                                                                       \
        pk2[(size_t)(S) * 32 + lane] = word;                                    \
        if (act) {                                                              \
            _Pragma("unroll")                                                   \
            for (int k = 0; k < CPL; k++) prev[k] = pf[k];                      \
        }                                                                       \
    }

    #pragma unroll 1
    for (int s = 1; s <= NSTEP; s += 8) {
        STEP(s,     B0) STEP(s + 1, B1) STEP(s + 2, B2) STEP(s + 3, B3)
        STEP(s + 4, B4) STEP(s + 5, B5) STEP(s + 6, B6) STEP(s + 7, B7)
    }
    #undef STEP
    #undef LOADBUF
}

// ---------------- post + traceback merged: one launch ----------------------
// blocks [0, PBLK): de-skew scores/pointers + boundaries (warp per (b,step))
// blocks [PBLK, PBLK+BS): traceback, one batch each
__global__ void posttb_kernel(float* __restrict__ out) {
    __shared__ unsigned chunkBuf[(CHUNK + 30) * 32];   // 19.8 KB

    if (blockIdx.x < PBLK) {
        int gtid = blockIdx.x * blockDim.x + threadIdx.x;
        int gw = gtid >> 5;
        int lane = gtid & 31;

        if (gw < WMAIN) {
            int b = gw / NSACT;
            int s = gw % NSACT + 1;
            int l = lane;
            int r = s - l;
            const float2* sp2 = (const float2*)(g_scr + (size_t)b * SKROW * 320) + (size_t)s * 160 + lane;
            float pf[CPL];
            #pragma unroll
            for (int q = 0; q < 5; q++) {
                float2 v = sp2[q * 32];
                pf[2*q] = v.x; pf[2*q+1] = v.y;
            }
            unsigned word = g_pk2[(size_t)b * SKROW * 32 + (size_t)s * 32 + lane];
            if (l < 30 && r >= 1 && r <= QN) {
                size_t rowoff = ((size_t)b * QP1 + r) * TP1 + 1 + l * CPL;
                float* dsts = out + rowoff;
                float* dstp = out + SCSZ + rowoff;
                #pragma unroll
                for (int k = 0; k < CPL; k++) {
                    unsigned e = (word >> (2 * k)) & 3u;
                    dsts[k] = pf[k];
                    dstp[k] = (e == 0u) ? 0.f : ((e == 1u) ? -1.f : 1.f);
                }
            }
        } else {
            int x = gtid - WMAIN * 32;
            if (x < NCOL0) {
                int i = x % QP1;
                int b = x / QP1;
                size_t o = ((size_t)b * QP1 + i) * TP1;
                out[o] = 0.f;
                out[SCSZ + o] = (i == 0) ? 0.f : -1.f;
            } else if (x < NCOL0 + NROW0) {
                int y = x - NCOL0;
                int j = (y % TN) + 1;
                int b = y / TN;
                size_t o = (size_t)b * QP1 * TP1 + j;
                out[o] = 0.f;
                out[SCSZ + o] = 1.f;
            }
        }
        return;
    }

    // ---- traceback blocks ----
    int b = blockIdx.x - PBLK;
    int tid = threadIdx.x;
    const unsigned* pk2 = g_pk2 + (size_t)b * SKROW * 32;
    float* mt = out + 2 * (size_t)SCSZ + (size_t)b * MTROW * 2;
    int r = QN, c = TN, st = 0;

    #pragma unroll 1
    for (int kk = 0; kk < QN / CHUNK; kk++) {
        int hi = QN - kk * CHUNK;
        int lo = hi - (CHUNK - 1);
        const unsigned* src = pk2 + (size_t)lo * 32;
        for (int x = tid; x < (CHUNK + 30) * 32; x += 128) chunkBuf[x] = src[x];
        __syncthreads();
        if (tid == 0) {
            while (st < MTROW && r >= lo) {
                int p;
                if (c == 0) {
                    p = -1;
                } else {
                    int ci = c - 1;
                    int l = ci / CPL;
                    unsigned wd = chunkBuf[(r + l - lo) * 32 + l];
                    int e = (wd >> (2 * (ci % CPL))) & 3;
                    p = (e == 0) ? 0 : ((e == 1) ? -1 : 1);
                }
                int nr = (p == 1) ? r : r - 1;
                int nc = (p == -1) ? c : c - 1;
                bool ismatch = (p == 0);
                int oidx = (MTROW - 1 - st) * 2;
                mt[oidx]     = ismatch ? (float)nr : -1.f;
                mt[oidx + 1] = ismatch ? (float)nc : -1.f;
                r = nr; c = nc; st++;
            }
        }
        __syncthreads();
    }
    if (tid == 0) {
        while (st < MTROW) {
            int oidx = (MTROW - 1 - st) * 2;
            mt[oidx] = -1.f;
            mt[oidx + 1] = -1.f;
            st++;
        }
    }
}

extern "C" void kernel_launch(void* const* d_in, const int* in_sizes, int n_in,
                              void* d_out, int out_size) {
    const float* pred_logits = (const float*)d_in[0];
    const float* pred_boxes  = (const float*)d_in[1];
    const int*   tgt_labels  = (const int*)d_in[2];
    const float* tgt_boxes   = (const float*)d_in[3];
    float* out = (float*)d_out;

    stat_kernel<<<(BS * QN + 7) / 8, 256>>>(pred_logits, (const unsigned*)d_in[2]);
    cost_kernel<<<(BS * NSACT * 320 + 255) / 256, 256>>>(pred_logits, pred_boxes,
                                                         tgt_labels, tgt_boxes);
    dp_kernel<<<BS, 32>>>();
    posttb_kernel<<<PBLK + BS, 128>>>(out);
}

// round 17
// speedup vs baseline: 1.2783x; 1.0827x over previous
#include <cuda_runtime.h>
#include <math.h>

#define BS 8
#define QN 1000
#define NC 92
#define TN 300
#define QP1 1001
#define TP1 301
#define SCSZ (BS*QP1*TP1)          // 2,410,408
#define MTROW (QN+TN)              // 1300
#define CPL 10
#define CHUNK 125
#define NSTEP 1032                 // >= QN+30 drain, multiple of 8
#define SKROW 1048                 // >= NSTEP + 8 prefetch
#define NSACT 1029                 // active steps (r in [1,QN], l in [0,30))
#define FULLM 0xffffffffu
#define NEGINF (-INFINITY)

#define WMAIN (BS*NSACT)           // post: warps over (b, step 1..1029)
#define NCOL0 (BS*QP1)
#define NROW0 (BS*TN)
#define PBLK ((WMAIN*32 + NCOL0 + NROW0 + 127)/128)   // post blocks

__device__ float2 g_sm[BS*QN];               // per-(b,q) softmax (max, sum)
__device__ float g_rwsk[BS*SKROW*320];       // rewards, skewed+paired
__device__ float g_scr[BS*SKROW*320];        // scores scratch, skewed+paired
__device__ unsigned g_pk2[BS*SKROW*32];      // 2-bit ptr codes (from dp)
__device__ int g_lbl64;

// ---------------- softmax stats + label dtype detection ----------------
__global__ void stat_kernel(const float* __restrict__ logits,
                            const unsigned* __restrict__ lbl_raw) {
    if (blockIdx.x == 0 && threadIdx.x == 0) {
        int allzero = 1;
        #pragma unroll
        for (int k = 1; k < 16; k += 2) allzero &= (lbl_raw[k] == 0u);
        g_lbl64 = allzero;
    }
    int warpId = (blockIdx.x * blockDim.x + threadIdx.x) >> 5;
    int lane = threadIdx.x & 31;
    if (warpId >= BS * QN) return;
    const float* row = logits + warpId * NC;
    float v0 = (lane < NC)      ? row[lane]      : NEGINF;
    float v1 = (lane + 32 < NC) ? row[lane + 32] : NEGINF;
    float v2 = (lane + 64 < NC) ? row[lane + 64] : NEGINF;
    float m = fmaxf(v0, fmaxf(v1, v2));
    #pragma unroll
    for (int o = 16; o; o >>= 1) m = fmaxf(m, __shfl_xor_sync(FULLM, m, o));
    float e0 = (lane < NC)      ? expf(v0 - m) : 0.f;
    float e1 = (lane + 32 < NC) ? expf(v1 - m) : 0.f;
    float e2 = (lane + 64 < NC) ? expf(v2 - m) : 0.f;
    float s = e0 + e1 + e2;
    #pragma unroll
    for (int o = 16; o; o >>= 1) s += __shfl_xor_sync(FULLM, s, o);
    if (lane == 0) g_sm[warpId] = make_float2(m, s);
}

// ---------------- cost v2: thread-per-slot, coalesced reward stores --------
__global__ void cost_kernel(const float* __restrict__ logits,
                            const float* __restrict__ pred_boxes,
                            const int* __restrict__ tgt_labels,
                            const float* __restrict__ tgt_boxes) {
    int idx = blockIdx.x * blockDim.x + threadIdx.x;
    if (idx >= BS * NSACT * 320) return;
    int slot = idx % 320;
    int bs_ = idx / 320;
    int s = bs_ % NSACT + 1;
    int b = bs_ / NSACT;
    int l = (slot & 63) >> 1;                 // lane
    int k = ((slot >> 6) << 1) + (slot & 1);  // strip col
    int r = s - l;
    if (l >= 30 || r < 1 || r > QN) return;
    int t = l * CPL + k;
    int bq = b * QN + (r - 1);

    float4 pb = ((const float4*)pred_boxes)[bq];
    float4 tb = ((const float4*)tgt_boxes)[b * TN + t];
    int li = b * TN + t;
    int lbl = g_lbl64 ? tgt_labels[li * 2] : tgt_labels[li];
    lbl = max(0, min(NC - 1, lbl));
    float2 ms = g_sm[bq];
    float p = expf(logits[bq * NC + lbl] - ms.x) / ms.y;

    float l1 = fabsf(pb.x - tb.x) + fabsf(pb.y - tb.y) +
               fabsf(pb.z - tb.z) + fabsf(pb.w - tb.w);

    float px1 = pb.x - 0.5f * pb.z, py1 = pb.y - 0.5f * pb.w;
    float px2 = pb.x + 0.5f * pb.z, py2 = pb.y + 0.5f * pb.w;
    float tx1 = tb.x - 0.5f * tb.z, ty1 = tb.y - 0.5f * tb.w;
    float tx2 = tb.x + 0.5f * tb.z, ty2 = tb.y + 0.5f * tb.w;

    float a1 = (px2 - px1) * (py2 - py1);
    float a2 = (tx2 - tx1) * (ty2 - ty1);
    float ltx = fmaxf(px1, tx1), lty = fmaxf(py1, ty1);
    float rbx = fminf(px2, tx2), rby = fminf(py2, ty2);
    float iw = fmaxf(rbx - ltx, 0.f), ih = fmaxf(rby - lty, 0.f);
    float inter = iw * ih;
    float uni = a1 + a2 - inter;
    float iou = inter / uni;
    float cx1 = fminf(px1, tx1), cy1 = fminf(py1, ty1);
    float cx2 = fmaxf(px2, tx2), cy2 = fmaxf(py2, ty2);
    float cw = fmaxf(cx2 - cx1, 0.f), ch = fmaxf(cy2 - cy1, 0.f);
    float ac = cw * ch;
    float giou = iou - (ac - uni) / ac;

    float cost = 5.0f * l1 - p - 2.0f * giou;
    g_rwsk[(size_t)b * SKROW * 320 + (size_t)s * 320 + slot] = 10000.0f - cost;
}

// ---------------- DP: one WARP per batch, wavefront, fused chain + codes ---
__global__ void __launch_bounds__(32, 1) dp_kernel() {
    int b = blockIdx.x;
    int lane = threadIdx.x;

    const float2* rwsk = (const float2*)(g_rwsk + (size_t)b * SKROW * 320);
    float2* scr = (float2*)(g_scr + (size_t)b * SKROW * 320);
    unsigned* pk2 = g_pk2 + (size_t)b * SKROW * 32;

    float prev[CPL];
    #pragma unroll
    for (int k = 0; k < CPL; k++) prev[k] = 0.f;
    float h1 = 0.f, h2 = 0.f;

    float2 B0[5], B1[5], B2[5], B3[5], B4[5], B5[5], B6[5], B7[5];

    #define LOADBUF(BUF, S)                                                     \
    {                                                                           \
        const float2* pp = rwsk + (size_t)(S) * 160 + lane;                     \
        _Pragma("unroll")                                                       \
        for (int q = 0; q < 5; q++) BUF[q] = pp[q * 32];                        \
    }

    LOADBUF(B0, 1) LOADBUF(B1, 2) LOADBUF(B2, 3) LOADBUF(B3, 4)
    LOADBUF(B4, 5) LOADBUF(B5, 6) LOADBUF(B6, 7) LOADBUF(B7, 8)

    #define STEP(S, BUF)                                                        \
    {                                                                           \
        int r = (S) - lane;                                                     \
        bool act = (lane < 30) && (r >= 1) && (r <= QN);                        \
        float X1 = __shfl_up_sync(FULLM, h1, 1);                                \
        float X2 = __shfl_up_sync(FULLM, h2, 1);                                \
        if (lane == 0) { X1 = NEGINF; X2 = 0.f; }                               \
        float rk[CPL];                                                          \
        _Pragma("unroll")                                                       \
        for (int q = 0; q < 5; q++) { rk[2*q] = BUF[q].x; rk[2*q+1] = BUF[q].y; } \
        LOADBUF(BUF, (S) + 8)                                                   \
        /* fused sequential prefix: 30 fma-pipe ops (issue-minimal) */          \
        float dg[CPL], pf[CPL];                                                 \
        dg[0] = X2 + rk[0];                                                     \
        _Pragma("unroll")                                                       \
        for (int k = 1; k < CPL; k++) dg[k] = prev[k-1] + rk[k];                \
        pf[0] = fmaxf(fmaxf(dg[0], prev[0]), X1);                               \
        _Pragma("unroll")                                                       \
        for (int k = 1; k < CPL; k++)                                           \
            pf[k] = fmaxf(fmaxf(dg[k], prev[k]), pf[k-1]);                      \
        h2 = h1;                                                                \
        h1 = act ? pf[CPL-1] : 0.f;                                             \
        float2* dsc = scr + (size_t)(S) * 160 + lane;                           \
        _Pragma("unroll")                                                       \
        for (int q = 0; q < 5; q++) dsc[q * 32] = make_float2(pf[2*q], pf[2*q+1]); \
        unsigned word = 0;                                                      \
        _Pragma("unroll")                                                       \
        for (int k = 0; k < CPL; k++) {                                         \
            unsigned e = (dg[k] == pf[k]) ? 0u : ((prev[k] == pf[k]) ? 1u : 2u);\
            word |= e << (2 * k);                                               \
        }                                                                       \
        pk2[(size_t)(S) * 32 + lane] = word;                                    \
        if (act) {                                                              \
            _Pragma("unroll")                                                   \
            for (int k = 0; k < CPL; k++) prev[k] = pf[k];                      \
        }                                                                       \
    }

    #pragma unroll 1
    for (int s = 1; s <= NSTEP; s += 8) {
        STEP(s,     B0) STEP(s + 1, B1) STEP(s + 2, B2) STEP(s + 3, B3)
        STEP(s + 4, B4) STEP(s + 5, B5) STEP(s + 6, B6) STEP(s + 7, B7)
    }
    #undef STEP
    #undef LOADBUF
}

// ---------------- post + traceback merged: one launch ----------------------
// blocks [0, PBLK): de-skew scores/pointers + boundaries (warp per (b,step))
// blocks [PBLK, PBLK+BS): traceback, one batch each (branch-free chase)
__global__ void posttb_kernel(float* __restrict__ out) {
    __shared__ unsigned chunkBuf[(CHUNK + 30) * 32];   // 19.8 KB

    if (blockIdx.x < PBLK) {
        int gtid = blockIdx.x * blockDim.x + threadIdx.x;
        int gw = gtid >> 5;
        int lane = gtid & 31;

        if (gw < WMAIN) {
            int b = gw / NSACT;
            int s = gw % NSACT + 1;
            int l = lane;
            int r = s - l;
            const float2* sp2 = (const float2*)(g_scr + (size_t)b * SKROW * 320) + (size_t)s * 160 + lane;
            float pf[CPL];
            #pragma unroll
            for (int q = 0; q < 5; q++) {
                float2 v = sp2[q * 32];
                pf[2*q] = v.x; pf[2*q+1] = v.y;
            }
            unsigned word = g_pk2[(size_t)b * SKROW * 32 + (size_t)s * 32 + lane];
            if (l < 30 && r >= 1 && r <= QN) {
                size_t rowoff = ((size_t)b * QP1 + r) * TP1 + 1 + l * CPL;
                float* dsts = out + rowoff;
                float* dstp = out + SCSZ + rowoff;
                #pragma unroll
                for (int k = 0; k < CPL; k++) {
                    unsigned e = (word >> (2 * k)) & 3u;
                    dsts[k] = pf[k];
                    dstp[k] = (e == 0u) ? 0.f : ((e == 1u) ? -1.f : 1.f);
                }
            }
        } else {
            int x = gtid - WMAIN * 32;
            if (x < NCOL0) {
                int i = x % QP1;
                int b = x / QP1;
                size_t o = ((size_t)b * QP1 + i) * TP1;
                out[o] = 0.f;
                out[SCSZ + o] = (i == 0) ? 0.f : -1.f;
            } else if (x < NCOL0 + NROW0) {
                int y = x - NCOL0;
                int j = (y % TN) + 1;
                int b = y / TN;
                size_t o = (size_t)b * QP1 * TP1 + j;
                out[o] = 0.f;
                out[SCSZ + o] = 1.f;
            }
        }
        return;
    }

    // ---- traceback blocks: branch-free predicated chase ----
    int b = blockIdx.x - PBLK;
    int tid = threadIdx.x;
    const unsigned* pk2 = g_pk2 + (size_t)b * SKROW * 32;
    float* mt = out + 2 * (size_t)SCSZ + (size_t)b * MTROW * 2;
    int r = QN, c = TN, st = 0;

    #pragma unroll 1
    for (int kk = 0; kk < QN / CHUNK; kk++) {
        int hi = QN - kk * CHUNK;
        int lo = hi - (CHUNK - 1);
        const unsigned* src = pk2 + (size_t)lo * 32;
        for (int x = tid; x < (CHUNK + 30) * 32; x += 128) chunkBuf[x] = src[x];
        __syncthreads();
        if (tid == 0) {
            // c >= 1 inside: once c hits 0, remaining path is all up-moves
            // emitting (-1,-1), identical to the tail fill below.
            while (st < MTROW && r >= lo && c > 0) {
                int ci = c - 1;
                int l = ci / CPL;                       // strip index
                unsigned wd = chunkBuf[(r + l - lo) * 32 + l];
                int e = (int)((wd >> (2 * (ci - l * CPL))) & 3u);
                int nr = r - ((e != 2) ? 1 : 0);        // SEL
                int nc = c - ((e != 1) ? 1 : 0);        // SEL
                bool md = (e == 0);
                int oidx = (MTROW - 1 - st) * 2;
                mt[oidx]     = md ? (float)nr : -1.f;   // SEL + STG
                mt[oidx + 1] = md ? (float)nc : -1.f;
                r = nr; c = nc; st++;
            }
        }
        __syncthreads();
    }
    if (tid == 0) {
        while (st < MTROW) {
            int oidx = (MTROW - 1 - st) * 2;
            mt[oidx] = -1.f;
            mt[oidx + 1] = -1.f;
            st++;
        }
    }
}

extern "C" void kernel_launch(void* const* d_in, const int* in_sizes, int n_in,
                              void* d_out, int out_size) {
    const float* pred_logits = (const float*)d_in[0];
    const float* pred_boxes  = (const float*)d_in[1];
    const int*   tgt_labels  = (const int*)d_in[2];
    const float* tgt_boxes   = (const float*)d_in[3];
    float* out = (float*)d_out;

    stat_kernel<<<(BS * QN + 7) / 8, 256>>>(pred_logits, (const unsigned*)d_in[2]);
    cost_kernel<<<(BS * NSACT * 320 + 255) / 256, 256>>>(pred_logits, pred_boxes,
                                                         tgt_labels, tgt_boxes);
    dp_kernel<<<BS, 32>>>();
    posttb_kernel<<<PBLK + BS, 128>>>(out);
}